// round 1
// baseline (speedup 1.0000x reference)
#include <cuda_runtime.h>
#include <math.h>

// Problem constants (fixed by setup_inputs: B=8, L=1024, E=8, D=512, 2 layers)
#define TOKENS 8192
#define DIM    512
#define NEXP   8
#define MAXE   64
#define LN_EPS 1e-5f

// ---------------- scratch (device globals; no allocation allowed) ----------
__device__ float g_m[TOKENS * DIM];   // weighted expert mean   [8192,512]
__device__ float g_z[TOKENS * DIM];   // gelu(GEMM) output      [8192,512]
__device__ float g_T1[DIM * DIM];     // W1 @ W0
__device__ float g_Wf[DIM * DIM];     // Wc @ W1 @ W0
__device__ float g_bf[DIM];           // fused bias
__device__ float g_tb[DIM];           // W1 @ b0
__device__ float g_v[NEXP];           // expert weighting vector
__device__ float g_s;                 // scalar s = sum(u)

// ---------------- structure: compute v, s from hyperedge indices ----------
__global__ void structure_kernel(const int* __restrict__ nodes,
                                 const int* __restrict__ edges, int nn) {
    // single-thread: E=8, num_edges <= 64, nn ~ 56. Trivial work.
    float deg[NEXP];
    float edeg[MAXE];
    int   Hc[NEXP][MAXE];
    for (int i = 0; i < NEXP; i++) {
        deg[i] = 0.0f;
        for (int e = 0; e < MAXE; e++) Hc[i][e] = 0;
    }
    for (int e = 0; e < MAXE; e++) edeg[e] = 0.0f;

    int ne = nn / 2;               // reference: num_edges = len(nodes_idx)//2
    if (ne > MAXE) ne = MAXE;

    for (int k = 0; k < nn; k++) {
        int i = nodes[k], e = edges[k];
        if (i < 0 || i >= NEXP || e < 0 || e >= ne) continue;
        Hc[i][e]++;
        deg[i]  += 1.0f;
        edeg[e] += 1.0f;
    }
    float dinv[NEXP], binv[MAXE];
    for (int i = 0; i < NEXP; i++) dinv[i] = deg[i] > 0.0f ? 1.0f / deg[i] : 0.0f;
    for (int e = 0; e < ne;  e++)  binv[e] = edeg[e] > 0.0f ? 1.0f / edeg[e] : 0.0f;

    // P = D^{-1} H B^{-1} H^T   (8x8)
    float P[NEXP][NEXP];
    for (int i = 0; i < NEXP; i++)
        for (int j = 0; j < NEXP; j++) {
            float acc = 0.0f;
            for (int e = 0; e < ne; e++)
                acc += (float)Hc[i][e] * binv[e] * (float)Hc[j][e];
            P[i][j] = dinv[i] * acc;
        }
    // u^T = (1/E) 1^T P ;  v^T = u^T P ;  s = sum(u)
    float u[NEXP], s = 0.0f;
    for (int j = 0; j < NEXP; j++) {
        float a = 0.0f;
        for (int i = 0; i < NEXP; i++) a += P[i][j];
        u[j] = a / (float)NEXP;
    }
    for (int j = 0; j < NEXP; j++) {
        float a = 0.0f;
        for (int i = 0; i < NEXP; i++) a += u[i] * P[i][j];
        g_v[j] = a;
    }
    for (int i = 0; i < NEXP; i++) s += u[i];
    g_s = s;
}

// ---------------- tiny GEMVs for the fused bias --------------------------
__global__ void gemv_tb_kernel(const float* __restrict__ W1,
                               const float* __restrict__ b0) {
    int j = blockIdx.x;
    float acc = 0.0f;
    for (int k = threadIdx.x; k < DIM; k += 128)
        acc += W1[j * DIM + k] * b0[k];
    for (int o = 16; o; o >>= 1) acc += __shfl_xor_sync(0xffffffffu, acc, o);
    __shared__ float sm[4];
    if ((threadIdx.x & 31) == 0) sm[threadIdx.x >> 5] = acc;
    __syncthreads();
    if (threadIdx.x == 0) g_tb[j] = sm[0] + sm[1] + sm[2] + sm[3];
}

__global__ void gemv_bf_kernel(const float* __restrict__ Wc,
                               const float* __restrict__ b1,
                               const float* __restrict__ cb) {
    int i = blockIdx.x;
    float s = g_s;
    float acc = 0.0f;
    for (int j = threadIdx.x; j < DIM; j += 128)
        acc += Wc[i * DIM + j] * (s * g_tb[j] + b1[j]);
    for (int o = 16; o; o >>= 1) acc += __shfl_xor_sync(0xffffffffu, acc, o);
    __shared__ float sm[4];
    if ((threadIdx.x & 31) == 0) sm[threadIdx.x >> 5] = acc;
    __syncthreads();
    if (threadIdx.x == 0) g_bf[i] = sm[0] + sm[1] + sm[2] + sm[3] + cb[i];
}

// ---------------- weighted expert reduction: m[n,d] = sum_e v[e]*x[n,e,d] -
__global__ void reduce_kernel(const float* __restrict__ x, int ntok) {
    int idx = blockIdx.x * blockDim.x + threadIdx.x;   // over ntok*128 float4
    int total = ntok * (DIM / 4);
    if (idx >= total) return;
    int n  = idx / (DIM / 4);
    int d4 = idx % (DIM / 4);
    const float4* base =
        reinterpret_cast<const float4*>(x) + (size_t)n * NEXP * (DIM / 4) + d4;
    float4 acc = make_float4(0.f, 0.f, 0.f, 0.f);
#pragma unroll
    for (int e = 0; e < NEXP; e++) {
        float4 v = base[(size_t)e * (DIM / 4)];
        float  w = g_v[e];
        acc.x += w * v.x; acc.y += w * v.y; acc.z += w * v.z; acc.w += w * v.w;
    }
    reinterpret_cast<float4*>(g_m)[idx] = acc;
}

// ---------------- exact GELU ----------------------------------------------
__device__ __forceinline__ float gelu_exact(float x) {
    return 0.5f * x * (1.0f + erff(x * 0.70710678118654752f));
}

// ---------------- tiled SGEMM ---------------------------------------------
// BT=true : B stored [N,K], C[m,n] = sum_k A[m,k]*B[n,k]   (C = A B^T)
// BT=false: B stored [K,N], C[m,n] = sum_k A[m,k]*B[k,n]   (C = A B)
// GB=true : C = gelu(acc + bias[n])
template <int BM, int BN, int BK, int TM, int TN, bool BT, bool GB>
__global__ __launch_bounds__((BM / TM) * (BN / TN)) void
sgemm_kernel(const float* __restrict__ A, const float* __restrict__ B,
             float* __restrict__ C, const float* __restrict__ bias,
             int M, int N, int K) {
    constexpr int THREADS = (BM / TM) * (BN / TN);
    __shared__ float As[BK][BM + 4];
    __shared__ float Bs[BK][BN + 4];

    const int tid = threadIdx.x;
    const int bm  = blockIdx.y * BM;
    const int bn  = blockIdx.x * BN;
    const int tx  = tid % (BN / TN);
    const int ty  = tid / (BN / TN);

    float acc[TM][TN];
#pragma unroll
    for (int i = 0; i < TM; i++)
#pragma unroll
        for (int j = 0; j < TN; j++) acc[i][j] = 0.0f;

    constexpr int A_PER = (BM * BK / 4) / THREADS;
    constexpr int B_PER = (BK * BN / 4) / THREADS;

    for (int k0 = 0; k0 < K; k0 += BK) {
        // A tile [BM x BK] from row-major [M,K], stored transposed As[k][m]
#pragma unroll
        for (int i = 0; i < A_PER; i++) {
            int idx = tid + i * THREADS;
            int row = idx / (BK / 4);
            int c4  = idx % (BK / 4);
            float4 v = *reinterpret_cast<const float4*>(
                &A[(size_t)(bm + row) * K + k0 + c4 * 4]);
            As[c4 * 4 + 0][row] = v.x;
            As[c4 * 4 + 1][row] = v.y;
            As[c4 * 4 + 2][row] = v.z;
            As[c4 * 4 + 3][row] = v.w;
        }
        if (BT) {
            // B tile rows bn.., cols k0..  -> Bs[k][n]
#pragma unroll
            for (int i = 0; i < B_PER; i++) {
                int idx = tid + i * THREADS;
                int row = idx / (BK / 4);
                int c4  = idx % (BK / 4);
                float4 v = *reinterpret_cast<const float4*>(
                    &B[(size_t)(bn + row) * K + k0 + c4 * 4]);
                Bs[c4 * 4 + 0][row] = v.x;
                Bs[c4 * 4 + 1][row] = v.y;
                Bs[c4 * 4 + 2][row] = v.z;
                Bs[c4 * 4 + 3][row] = v.w;
            }
        } else {
            // B tile rows k0..k0+BK, cols bn..  -> Bs[k][n]
#pragma unroll
            for (int i = 0; i < B_PER; i++) {
                int idx  = tid + i * THREADS;
                int krow = idx / (BN / 4);
                int c4   = idx % (BN / 4);
                float4 v = *reinterpret_cast<const float4*>(
                    &B[(size_t)(k0 + krow) * N + bn + c4 * 4]);
                *reinterpret_cast<float4*>(&Bs[krow][c4 * 4]) = v;
            }
        }
        __syncthreads();

#pragma unroll
        for (int k = 0; k < BK; k++) {
            float ra[TM], rb[TN];
#pragma unroll
            for (int i = 0; i < TM; i++) ra[i] = As[k][ty * TM + i];
#pragma unroll
            for (int j = 0; j < TN; j++) rb[j] = Bs[k][tx * TN + j];
#pragma unroll
            for (int i = 0; i < TM; i++)
#pragma unroll
                for (int j = 0; j < TN; j++) acc[i][j] += ra[i] * rb[j];
        }
        __syncthreads();
    }

#pragma unroll
    for (int i = 0; i < TM; i++) {
        int row = bm + ty * TM + i;
#pragma unroll
        for (int j = 0; j < TN; j += 4) {
            int col = bn + tx * TN + j;
            float4 v;
            if (GB) {
                v.x = gelu_exact(acc[i][j + 0] + bias[col + 0]);
                v.y = gelu_exact(acc[i][j + 1] + bias[col + 1]);
                v.z = gelu_exact(acc[i][j + 2] + bias[col + 2]);
                v.w = gelu_exact(acc[i][j + 3] + bias[col + 3]);
            } else {
                v.x = acc[i][j + 0];
                v.y = acc[i][j + 1];
                v.z = acc[i][j + 2];
                v.w = acc[i][j + 3];
            }
            *reinterpret_cast<float4*>(&C[(size_t)row * N + col]) = v;
        }
    }
}

// ---------------- LayerNorm over last dim (D=512), one block per row ------
__global__ void ln_kernel(const float* __restrict__ z,
                          const float* __restrict__ gamma,
                          const float* __restrict__ beta,
                          float* __restrict__ out) {
    int row = blockIdx.x;
    int t   = threadIdx.x;  // 128 threads, float4 each = 512
    const float4* zr = reinterpret_cast<const float4*>(z) + (size_t)row * 128;
    float4 v = zr[t];
    float s = v.x + v.y + v.z + v.w;
    float q = v.x * v.x + v.y * v.y + v.z * v.z + v.w * v.w;
    for (int o = 16; o; o >>= 1) {
        s += __shfl_xor_sync(0xffffffffu, s, o);
        q += __shfl_xor_sync(0xffffffffu, q, o);
    }
    __shared__ float ss[4], sq[4];
    if ((t & 31) == 0) { ss[t >> 5] = s; sq[t >> 5] = q; }
    __syncthreads();
    s = ss[0] + ss[1] + ss[2] + ss[3];
    q = sq[0] + sq[1] + sq[2] + sq[3];
    float mu  = s * (1.0f / DIM);
    float var = q * (1.0f / DIM) - mu * mu;
    float inv = rsqrtf(var + LN_EPS);
    float4 g = reinterpret_cast<const float4*>(gamma)[t];
    float4 b = reinterpret_cast<const float4*>(beta)[t];
    float4 o;
    o.x = (v.x - mu) * inv * g.x + b.x;
    o.y = (v.y - mu) * inv * g.y + b.y;
    o.z = (v.z - mu) * inv * g.z + b.z;
    o.w = (v.w - mu) * inv * g.w + b.w;
    (reinterpret_cast<float4*>(out) + (size_t)row * 128)[t] = o;
}

// ---------------- launcher -------------------------------------------------
extern "C" void kernel_launch(void* const* d_in, const int* in_sizes, int n_in,
                              void* d_out, int out_size) {
    const float* x     = (const float*)d_in[0];  // [8,1024,8,512]
    const float* hw    = (const float*)d_in[1];  // [2,512,512]
    const float* hb    = (const float*)d_in[2];  // [2,512]
    const float* cw    = (const float*)d_in[3];  // [512,512]
    const float* cbias = (const float*)d_in[4];  // [512]
    const float* lg    = (const float*)d_in[5];  // [512]
    const float* lb    = (const float*)d_in[6];  // [512]
    const int*   nodes = (const int*)d_in[7];
    const int*   edges = (const int*)d_in[8];
    const int    nn    = in_sizes[7];
    float*       out   = (float*)d_out;

    const int ntok = in_sizes[0] / (NEXP * DIM);  // 8192

    float *pT1, *pWf, *pm, *pz, *pbf;
    cudaGetSymbolAddress((void**)&pT1, g_T1);
    cudaGetSymbolAddress((void**)&pWf, g_Wf);
    cudaGetSymbolAddress((void**)&pm,  g_m);
    cudaGetSymbolAddress((void**)&pz,  g_z);
    cudaGetSymbolAddress((void**)&pbf, g_bf);

    const float* W0 = hw;             // layer 0 weight
    const float* W1 = hw + DIM * DIM; // layer 1 weight
    const float* b0 = hb;
    const float* b1 = hb + DIM;

    // 1) hyperedge structure -> v, s
    structure_kernel<<<1, 1>>>(nodes, edges, nn);

    // 2) weighted expert mean (independent of structure GEMMs; needs g_v)
    {
        int total  = ntok * (DIM / 4);
        int blocks = (total + 255) / 256;
        reduce_kernel<<<blocks, 256>>>(x, ntok);
    }

    // 3) fused weight: Wf = Wc @ W1 @ W0   (two 512^3 GEMMs, NN form)
    {
        dim3 grid(DIM / 64, DIM / 64);
        sgemm_kernel<64, 64, 16, 4, 4, false, false>
            <<<grid, 256>>>(W1, W0, pT1, nullptr, DIM, DIM, DIM);
        sgemm_kernel<64, 64, 16, 4, 4, false, false>
            <<<grid, 256>>>(cw, pT1, pWf, nullptr, DIM, DIM, DIM);
    }

    // 4) fused bias: bf = Wc @ (s*(W1@b0) + b1) + cb
    gemv_tb_kernel<<<DIM, 128>>>(W1, b0);
    gemv_bf_kernel<<<DIM, 128>>>(cw, b1, cbias);

    // 5) main GEMM + bias + exact GELU: z = gelu(m @ Wf^T + bf)
    {
        dim3 grid(DIM / 128, ntok / 128);
        sgemm_kernel<128, 128, 16, 8, 8, true, true>
            <<<grid, 256>>>(pm, pWf, pz, pbf, ntok, DIM, DIM);
    }

    // 6) LayerNorm -> out
    ln_kernel<<<ntok, 128>>>(pz, lg, lb, out);
}

// round 3
// speedup vs baseline: 1.6549x; 1.6549x over previous
#include <cuda_runtime.h>
#include <cuda_bf16.h>
#include <math.h>
#include <stdint.h>

// Problem constants (fixed: B=8, L=1024, E=8, D=512, 2 layers)
#define TOKENS 8192
#define DIM    512
#define NEXP   8
#define MAXE   64
#define LN_EPS 1e-5f

// ---------------- scratch (device globals) ---------------------------------
__device__ float          g_z[TOKENS * DIM];     // gelu(GEMM) output
__device__ __nv_bfloat16  g_mh[TOKENS * DIM];    // m hi
__device__ __nv_bfloat16  g_ml[TOKENS * DIM];    // m lo
__device__ __nv_bfloat16  g_wh[DIM * DIM];       // Wf hi
__device__ __nv_bfloat16  g_wl[DIM * DIM];       // Wf lo
__device__ float          g_T1[DIM * DIM];       // W1 @ W0
__device__ float          g_part[4 * DIM * DIM]; // split-K partials
__device__ float          g_bf[DIM];
__device__ float          g_tb[DIM];
__device__ float          g_v[NEXP];
__device__ float          g_s;

// ---------------- structure: compute v, s from hyperedge indices ----------
__global__ void structure_kernel(const int* __restrict__ nodes,
                                 const int* __restrict__ edges, int nn) {
    float deg[NEXP];
    float edeg[MAXE];
    int   Hc[NEXP][MAXE];
    for (int i = 0; i < NEXP; i++) {
        deg[i] = 0.0f;
        for (int e = 0; e < MAXE; e++) Hc[i][e] = 0;
    }
    for (int e = 0; e < MAXE; e++) edeg[e] = 0.0f;

    int ne = nn / 2;
    if (ne > MAXE) ne = MAXE;

    for (int k = 0; k < nn; k++) {
        int i = nodes[k], e = edges[k];
        if (i < 0 || i >= NEXP || e < 0 || e >= ne) continue;
        Hc[i][e]++;
        deg[i]  += 1.0f;
        edeg[e] += 1.0f;
    }
    float dinv[NEXP], binv[MAXE];
    for (int i = 0; i < NEXP; i++) dinv[i] = deg[i] > 0.0f ? 1.0f / deg[i] : 0.0f;
    for (int e = 0; e < ne;  e++)  binv[e] = edeg[e] > 0.0f ? 1.0f / edeg[e] : 0.0f;

    float P[NEXP][NEXP];
    for (int i = 0; i < NEXP; i++)
        for (int j = 0; j < NEXP; j++) {
            float acc = 0.0f;
            for (int e = 0; e < ne; e++)
                acc += (float)Hc[i][e] * binv[e] * (float)Hc[j][e];
            P[i][j] = dinv[i] * acc;
        }
    float u[NEXP], s = 0.0f;
    for (int j = 0; j < NEXP; j++) {
        float a = 0.0f;
        for (int i = 0; i < NEXP; i++) a += P[i][j];
        u[j] = a / (float)NEXP;
    }
    for (int j = 0; j < NEXP; j++) {
        float a = 0.0f;
        for (int i = 0; i < NEXP; i++) a += u[i] * P[i][j];
        g_v[j] = a;
    }
    for (int i = 0; i < NEXP; i++) s += u[i];
    g_s = s;
}

// ---------------- tiny GEMVs -----------------------------------------------
__global__ void gemv_tb_kernel(const float* __restrict__ W1,
                               const float* __restrict__ b0) {
    int j = blockIdx.x;
    float acc = 0.0f;
    for (int k = threadIdx.x; k < DIM; k += 128)
        acc += W1[j * DIM + k] * b0[k];
    for (int o = 16; o; o >>= 1) acc += __shfl_xor_sync(0xffffffffu, acc, o);
    __shared__ float sm[4];
    if ((threadIdx.x & 31) == 0) sm[threadIdx.x >> 5] = acc;
    __syncthreads();
    if (threadIdx.x == 0) g_tb[j] = sm[0] + sm[1] + sm[2] + sm[3];
}

__global__ void gemv_bf_kernel(const float* __restrict__ Wc,
                               const float* __restrict__ b1,
                               const float* __restrict__ cb) {
    int i = blockIdx.x;
    float s = g_s;
    float acc = 0.0f;
    for (int j = threadIdx.x; j < DIM; j += 128)
        acc += Wc[i * DIM + j] * (s * g_tb[j] + b1[j]);
    for (int o = 16; o; o >>= 1) acc += __shfl_xor_sync(0xffffffffu, acc, o);
    __shared__ float sm[4];
    if ((threadIdx.x & 31) == 0) sm[threadIdx.x >> 5] = acc;
    __syncthreads();
    if (threadIdx.x == 0) g_bf[i] = sm[0] + sm[1] + sm[2] + sm[3] + cb[i];
}

// ---------------- hi/lo bf16 split -----------------------------------------
__device__ __forceinline__ void split_bf16(float x, __nv_bfloat16& h,
                                           __nv_bfloat16& l) {
    h = __float2bfloat16(x);
    l = __float2bfloat16(x - __bfloat162float(h));
}

// ---------------- weighted expert reduce -> bf16 hi/lo ---------------------
__global__ void reduce_convert_kernel(const float* __restrict__ x) {
    int idx = blockIdx.x * blockDim.x + threadIdx.x;  // over TOKENS*128 float4
    int n  = idx >> 7;
    int d4 = idx & 127;
    const float4* base =
        reinterpret_cast<const float4*>(x) + (size_t)n * NEXP * 128 + d4;
    float4 acc = make_float4(0.f, 0.f, 0.f, 0.f);
#pragma unroll
    for (int e = 0; e < NEXP; e++) {
        float4 v = base[(size_t)e * 128];
        float  w = g_v[e];
        acc.x += w * v.x; acc.y += w * v.y; acc.z += w * v.z; acc.w += w * v.w;
    }
    __nv_bfloat16 h0, h1, h2, h3, l0, l1, l2, l3;
    split_bf16(acc.x, h0, l0); split_bf16(acc.y, h1, l1);
    split_bf16(acc.z, h2, l2); split_bf16(acc.w, h3, l3);
    __nv_bfloat162* mh = reinterpret_cast<__nv_bfloat162*>(g_mh);
    __nv_bfloat162* ml = reinterpret_cast<__nv_bfloat162*>(g_ml);
    mh[idx * 2 + 0] = __halves2bfloat162(h0, h1);
    mh[idx * 2 + 1] = __halves2bfloat162(h2, h3);
    ml[idx * 2 + 0] = __halves2bfloat162(l0, l1);
    ml[idx * 2 + 1] = __halves2bfloat162(l2, l3);
}

// ---------------- split-K 512^3 SGEMM (NN) ----------------------------------
__global__ __launch_bounds__(256) void sgemm512_sk(const float* __restrict__ A,
                                                   const float* __restrict__ B) {
    __shared__ float As[16][68];
    __shared__ float Bs[16][68];
    const int tid = threadIdx.x;
    const int bm = blockIdx.y * 64, bn = blockIdx.x * 64;
    const int kz = blockIdx.z * 128;
    const int tx = tid & 15, ty = tid >> 4;

    float acc[4][4];
#pragma unroll
    for (int i = 0; i < 4; i++)
#pragma unroll
        for (int j = 0; j < 4; j++) acc[i][j] = 0.0f;

    for (int k0 = kz; k0 < kz + 128; k0 += 16) {
        {
            int row = tid >> 2, c4 = tid & 3;
            float4 v = *reinterpret_cast<const float4*>(
                &A[(size_t)(bm + row) * DIM + k0 + c4 * 4]);
            As[c4 * 4 + 0][row] = v.x; As[c4 * 4 + 1][row] = v.y;
            As[c4 * 4 + 2][row] = v.z; As[c4 * 4 + 3][row] = v.w;
        }
        {
            int krow = tid >> 4, c4 = tid & 15;
            float4 v = *reinterpret_cast<const float4*>(
                &B[(size_t)(k0 + krow) * DIM + bn + c4 * 4]);
            *reinterpret_cast<float4*>(&Bs[krow][c4 * 4]) = v;
        }
        __syncthreads();
#pragma unroll
        for (int k = 0; k < 16; k++) {
            float ra[4], rb[4];
#pragma unroll
            for (int i = 0; i < 4; i++) ra[i] = As[k][ty * 4 + i];
#pragma unroll
            for (int j = 0; j < 4; j++) rb[j] = Bs[k][tx * 4 + j];
#pragma unroll
            for (int i = 0; i < 4; i++)
#pragma unroll
                for (int j = 0; j < 4; j++) acc[i][j] += ra[i] * rb[j];
        }
        __syncthreads();
    }
    float* out = g_part + (size_t)blockIdx.z * DIM * DIM;
#pragma unroll
    for (int i = 0; i < 4; i++) {
        int row = bm + ty * 4 + i;
        float4 v = make_float4(acc[i][0], acc[i][1], acc[i][2], acc[i][3]);
        *reinterpret_cast<float4*>(&out[(size_t)row * DIM + bn + tx * 4]) = v;
    }
}

__global__ void combine_to_T1(void) {
    int i = blockIdx.x * 256 + threadIdx.x;
    const float4* p = reinterpret_cast<const float4*>(g_part);
    float4 a = p[i], b = p[i + 65536], c = p[i + 131072], d = p[i + 196608];
    float4 s = make_float4(a.x + b.x + c.x + d.x, a.y + b.y + c.y + d.y,
                           a.z + b.z + c.z + d.z, a.w + b.w + c.w + d.w);
    reinterpret_cast<float4*>(g_T1)[i] = s;
}

__global__ void combine_to_W(void) {
    int i = blockIdx.x * 256 + threadIdx.x;
    const float4* p = reinterpret_cast<const float4*>(g_part);
    float4 a = p[i], b = p[i + 65536], c = p[i + 131072], d = p[i + 196608];
    float4 s = make_float4(a.x + b.x + c.x + d.x, a.y + b.y + c.y + d.y,
                           a.z + b.z + c.z + d.z, a.w + b.w + c.w + d.w);
    __nv_bfloat16 h0, h1, h2, h3, l0, l1, l2, l3;
    split_bf16(s.x, h0, l0); split_bf16(s.y, h1, l1);
    split_bf16(s.z, h2, l2); split_bf16(s.w, h3, l3);
    __nv_bfloat162* wh = reinterpret_cast<__nv_bfloat162*>(g_wh);
    __nv_bfloat162* wl = reinterpret_cast<__nv_bfloat162*>(g_wl);
    wh[i * 2 + 0] = __halves2bfloat162(h0, h1);
    wh[i * 2 + 1] = __halves2bfloat162(h2, h3);
    wl[i * 2 + 0] = __halves2bfloat162(l0, l1);
    wl[i * 2 + 1] = __halves2bfloat162(l2, l3);
}

// ---------------- exact GELU -----------------------------------------------
__device__ __forceinline__ float gelu_exact(float x) {
    return 0.5f * x * (1.0f + erff(x * 0.70710678118654752f));
}

// ---------------- HMMA main GEMM (baseline PTX, no tcgen05) -----------------
// z = gelu(m @ Wf^T + bf), M=8192, N=512, K=512.
// bf16 hi/lo compensated: acc = Ah*Bh + Ah*Bl + Al*Bh in fp32.
// CTA tile 128x128, 8 warps (warp tile 32x64), BK=32, cp.async double buffer.
#define BK  32
#define BKP 40                      // padded row stride (bf16 elems)
#define TILE_E (128 * BKP)          // 5120 elems = 10240 B
#define STG_E  (4 * TILE_E)         // Ah, Al, Bh, Bl
#define GEMM_SMEM_B (2 * STG_E * 2) // 81920 bytes

__device__ __forceinline__ void cp_async16(uint32_t saddr, const void* gptr) {
    asm volatile("cp.async.cg.shared.global [%0], [%1], 16;\n"
                 :: "r"(saddr), "l"(gptr));
}
__device__ __forceinline__ void cp_commit() {
    asm volatile("cp.async.commit_group;\n");
}
template <int N>
__device__ __forceinline__ void cp_wait() {
    asm volatile("cp.async.wait_group %0;\n" :: "n"(N));
}
__device__ __forceinline__ void ldsm_x4(uint32_t* r, uint32_t addr) {
    asm volatile(
        "ldmatrix.sync.aligned.m8n8.x4.shared.b16 {%0,%1,%2,%3}, [%4];"
        : "=r"(r[0]), "=r"(r[1]), "=r"(r[2]), "=r"(r[3]) : "r"(addr));
}
__device__ __forceinline__ void mma_bf16(float* d, const uint32_t* a,
                                         uint32_t b0, uint32_t b1) {
    asm volatile(
        "mma.sync.aligned.m16n8k16.row.col.f32.bf16.bf16.f32 "
        "{%0,%1,%2,%3}, {%4,%5,%6,%7}, {%8,%9}, {%0,%1,%2,%3};"
        : "+f"(d[0]), "+f"(d[1]), "+f"(d[2]), "+f"(d[3])
        : "r"(a[0]), "r"(a[1]), "r"(a[2]), "r"(a[3]), "r"(b0), "r"(b1));
}
__device__ __forceinline__ uint32_t smem_u32(const void* p) {
    uint32_t a;
    asm("{ .reg .u64 t; cvta.to.shared.u64 t, %1; cvt.u32.u64 %0, t; }"
        : "=r"(a) : "l"(p));
    return a;
}

__global__ __launch_bounds__(256, 1) void gemm_mma(void) {
    extern __shared__ __nv_bfloat16 smem[];
    const uint32_t sb = smem_u32(smem);
    const int tid  = threadIdx.x;
    const int wid  = tid >> 5;
    const int lane = tid & 31;
    const int bm = blockIdx.y * 128;
    const int bn = blockIdx.x * 128;
    const int wm0 = (wid & 3) * 32;   // warp m offset within CTA
    const int wn0 = (wid >> 2) * 64;  // warp n offset within CTA

    float acc[2][8][4];
#pragma unroll
    for (int i = 0; i < 2; i++)
#pragma unroll
        for (int j = 0; j < 8; j++)
#pragma unroll
            for (int r = 0; r < 4; r++) acc[i][j][r] = 0.0f;

    // ldmatrix lane address components
    const int lrow = (lane & 7) + ((lane >> 3) & 1) * 8;
    const int lcol = (lane >> 4) * 8;
    const uint32_t a_elem = (uint32_t)((wm0 + lrow) * BKP + lcol);
    const uint32_t b_elem = (uint32_t)((wn0 + lrow) * BKP + lcol);

    // cp.async source/dst components: per tile, thread covers 2 of 512 uint4
    const int r_ld = tid >> 2;        // row 0..63  (+64 on second j)
    const int u_ld = tid & 3;         // uint4 within 32-bf16 row

    // issue one stage of loads into buffer `buf`
    auto issue_stage = [&](int c, int buf) {
        const int k0 = c * BK;
        const uint32_t stg = sb + (uint32_t)(buf * STG_E * 2);
#pragma unroll
        for (int j = 0; j < 2; j++) {
            const int r = r_ld + j * 64;
            const uint32_t doff = (uint32_t)((r * BKP + u_ld * 8) * 2);
            const __nv_bfloat16* sAh = g_mh + (size_t)(bm + r) * DIM + k0 + u_ld * 8;
            const __nv_bfloat16* sAl = g_ml + (size_t)(bm + r) * DIM + k0 + u_ld * 8;
            const __nv_bfloat16* sBh = g_wh + (size_t)(bn + r) * DIM + k0 + u_ld * 8;
            const __nv_bfloat16* sBl = g_wl + (size_t)(bn + r) * DIM + k0 + u_ld * 8;
            cp_async16(stg + 0 * TILE_E * 2 + doff, sAh);
            cp_async16(stg + 1 * TILE_E * 2 + doff, sAl);
            cp_async16(stg + 2 * TILE_E * 2 + doff, sBh);
            cp_async16(stg + 3 * TILE_E * 2 + doff, sBl);
        }
    };

    issue_stage(0, 0);
    cp_commit();

    const int NSTG = DIM / BK;  // 16
    for (int c = 0; c < NSTG; c++) {
        const int buf = c & 1;
        if (c + 1 < NSTG) { issue_stage(c + 1, (c + 1) & 1); cp_commit(); }
        if (c + 1 < NSTG) cp_wait<1>(); else cp_wait<0>();
        __syncthreads();

        const uint32_t stg = sb + (uint32_t)(buf * STG_E * 2);
        const uint32_t pAh = stg + 0 * TILE_E * 2 + a_elem * 2;
        const uint32_t pAl = stg + 1 * TILE_E * 2 + a_elem * 2;
        const uint32_t pBh = stg + 2 * TILE_E * 2 + b_elem * 2;
        const uint32_t pBl = stg + 3 * TILE_E * 2 + b_elem * 2;

#pragma unroll
        for (int kk = 0; kk < BK; kk += 16) {
            uint32_t Ah[2][4], Al[2][4], Bh[4][4], Bl[4][4];
#pragma unroll
            for (int mi = 0; mi < 2; mi++) {
                const uint32_t o = (uint32_t)((mi * 16 * BKP + kk) * 2);
                ldsm_x4(Ah[mi], pAh + o);
                ldsm_x4(Al[mi], pAl + o);
            }
#pragma unroll
            for (int ng = 0; ng < 4; ng++) {
                const uint32_t o = (uint32_t)((ng * 16 * BKP + kk) * 2);
                ldsm_x4(Bh[ng], pBh + o);
                ldsm_x4(Bl[ng], pBl + o);
            }
#pragma unroll
            for (int mi = 0; mi < 2; mi++) {
#pragma unroll
                for (int n8 = 0; n8 < 8; n8++) {
                    const int ng = n8 >> 1, hf = n8 & 1;
                    const uint32_t bh0 = Bh[ng][hf], bh1 = Bh[ng][hf + 2];
                    const uint32_t bl0 = Bl[ng][hf], bl1 = Bl[ng][hf + 2];
                    mma_bf16(acc[mi][n8], Ah[mi], bh0, bh1);
                    mma_bf16(acc[mi][n8], Ah[mi], bl0, bl1);
                    mma_bf16(acc[mi][n8], Al[mi], bh0, bh1);
                }
            }
        }
        __syncthreads();
    }

    // epilogue: acc[mi][n8][0..3] -> rows (bm+wm0+mi*16+lane/4, +8),
    //           cols (bn+wn0+n8*8+2*(lane%3)... 2*(lane&3), +1)
    const int row0 = bm + wm0 + (lane >> 2);
    const int col0 = bn + wn0 + (lane & 3) * 2;
#pragma unroll
    for (int mi = 0; mi < 2; mi++) {
#pragma unroll
        for (int n8 = 0; n8 < 8; n8++) {
            const int c = col0 + n8 * 8;
            const float b0 = g_bf[c], b1 = g_bf[c + 1];
            const int rA = row0 + mi * 16;
            float2 v0, v1;
            v0.x = gelu_exact(acc[mi][n8][0] + b0);
            v0.y = gelu_exact(acc[mi][n8][1] + b1);
            v1.x = gelu_exact(acc[mi][n8][2] + b0);
            v1.y = gelu_exact(acc[mi][n8][3] + b1);
            *reinterpret_cast<float2*>(&g_z[(size_t)rA * DIM + c])       = v0;
            *reinterpret_cast<float2*>(&g_z[(size_t)(rA + 8) * DIM + c]) = v1;
        }
    }
}

// ---------------- LayerNorm -------------------------------------------------
__global__ void ln_kernel(const float* __restrict__ gamma,
                          const float* __restrict__ beta,
                          float* __restrict__ out) {
    int row = blockIdx.x;
    int t   = threadIdx.x;
    const float4* zr = reinterpret_cast<const float4*>(g_z) + (size_t)row * 128;
    float4 v = zr[t];
    float s = v.x + v.y + v.z + v.w;
    float q = v.x * v.x + v.y * v.y + v.z * v.z + v.w * v.w;
    for (int o = 16; o; o >>= 1) {
        s += __shfl_xor_sync(0xffffffffu, s, o);
        q += __shfl_xor_sync(0xffffffffu, q, o);
    }
    __shared__ float ss[4], sq[4];
    if ((t & 31) == 0) { ss[t >> 5] = s; sq[t >> 5] = q; }
    __syncthreads();
    s = ss[0] + ss[1] + ss[2] + ss[3];
    q = sq[0] + sq[1] + sq[2] + sq[3];
    float mu  = s * (1.0f / DIM);
    float var = q * (1.0f / DIM) - mu * mu;
    float inv = rsqrtf(var + LN_EPS);
    float4 g = reinterpret_cast<const float4*>(gamma)[t];
    float4 b = reinterpret_cast<const float4*>(beta)[t];
    float4 o;
    o.x = (v.x - mu) * inv * g.x + b.x;
    o.y = (v.y - mu) * inv * g.y + b.y;
    o.z = (v.z - mu) * inv * g.z + b.z;
    o.w = (v.w - mu) * inv * g.w + b.w;
    (reinterpret_cast<float4*>(out) + (size_t)row * 128)[t] = o;
}

// ---------------- launcher ---------------------------------------------------
extern "C" void kernel_launch(void* const* d_in, const int* in_sizes, int n_in,
                              void* d_out, int out_size) {
    const float* x     = (const float*)d_in[0];
    const float* hw    = (const float*)d_in[1];
    const float* hb    = (const float*)d_in[2];
    const float* cw    = (const float*)d_in[3];
    const float* cbias = (const float*)d_in[4];
    const float* lg    = (const float*)d_in[5];
    const float* lb    = (const float*)d_in[6];
    const int*   nodes = (const int*)d_in[7];
    const int*   edges = (const int*)d_in[8];
    const int    nn    = in_sizes[7];
    float*       out   = (float*)d_out;

    const float* W0 = hw;
    const float* W1 = hw + DIM * DIM;
    const float* b0 = hb;
    const float* b1 = hb + DIM;

    float* pT1 = nullptr;
    cudaGetSymbolAddress((void**)&pT1, g_T1);

    cudaFuncSetAttribute(gemm_mma, cudaFuncAttributeMaxDynamicSharedMemorySize,
                         GEMM_SMEM_B);

    // 1) hyperedge structure -> v, s
    structure_kernel<<<1, 1>>>(nodes, edges, nn);

    // 2) weighted expert reduce -> m hi/lo bf16
    reduce_convert_kernel<<<TOKENS * 128 / 256, 256>>>(x);

    // 3) Wf = Wc @ (W1 @ W0), split-K small GEMMs
    {
        dim3 grid(8, 8, 4);
        sgemm512_sk<<<grid, 256>>>(W1, W0);
        combine_to_T1<<<256, 256>>>();
        sgemm512_sk<<<grid, 256>>>(cw, pT1);
        combine_to_W<<<256, 256>>>();
    }

    // 4) fused bias
    gemv_tb_kernel<<<DIM, 128>>>(W1, b0);
    gemv_bf_kernel<<<DIM, 128>>>(cw, b1, cbias);

    // 5) main HMMA GEMM + bias + GELU
    {
        dim3 grid(DIM / 128, TOKENS / 128);
        gemm_mma<<<grid, 256, GEMM_SMEM_B>>>();
    }

    // 6) LayerNorm
    ln_kernel<<<TOKENS, 128>>>(lg, lb, out);
}

// round 4
// speedup vs baseline: 1.9567x; 1.1824x over previous
#include <cuda_runtime.h>
#include <cuda_bf16.h>
#include <math.h>
#include <stdint.h>

// Problem constants (fixed: B=8, L=1024, E=8, D=512, 2 layers)
#define TOKENS 8192
#define DIM    512
#define NEXP   8
#define MAXE   64
#define LN_EPS 1e-5f

// ---------------- scratch (device globals) ---------------------------------
__device__ __nv_bfloat16  g_mh[TOKENS * DIM];     // m hi
__device__ __nv_bfloat16  g_ml[TOKENS * DIM];     // m lo
__device__ __nv_bfloat16  g_wh[DIM * DIM];        // Wf hi
__device__ __nv_bfloat16  g_wl[DIM * DIM];        // Wf lo
__device__ float          g_part[4 * DIM * DIM];  // split-K partials (T1)
__device__ float          g_part2[4 * DIM * DIM]; // split-K partials (Wf)
__device__ float          g_bf[DIM];
__device__ float          g_tb[DIM];
__device__ float          g_v[NEXP];
__device__ float          g_s;

// ---------------- structure: compute v, s (parallel, 1 block) --------------
__global__ void structure_kernel(const int* __restrict__ nodes,
                                 const int* __restrict__ edges, int nn) {
    __shared__ float deg[NEXP];
    __shared__ float edeg[MAXE];
    __shared__ int   Hc[NEXP][MAXE];
    __shared__ float P[NEXP][NEXP];
    __shared__ float u[NEXP];
    const int t = threadIdx.x;  // 256 threads

    if (t < NEXP) deg[t] = 0.0f;
    if (t < MAXE) edeg[t] = 0.0f;
    for (int i = t; i < NEXP * MAXE; i += 256) (&Hc[0][0])[i] = 0;
    __syncthreads();

    int ne = nn / 2;
    if (ne > MAXE) ne = MAXE;
    for (int k = t; k < nn; k += 256) {
        int i = nodes[k], e = edges[k];
        if (i < 0 || i >= NEXP || e < 0 || e >= ne) continue;
        atomicAdd(&Hc[i][e], 1);
        atomicAdd(&deg[i], 1.0f);
        atomicAdd(&edeg[e], 1.0f);
    }
    __syncthreads();

    if (t < NEXP * NEXP) {
        int i = t >> 3, j = t & 7;
        float acc = 0.0f;
        for (int e = 0; e < ne; e++) {
            float binv = edeg[e] > 0.0f ? 1.0f / edeg[e] : 0.0f;
            acc += (float)Hc[i][e] * binv * (float)Hc[j][e];
        }
        float dinv = deg[i] > 0.0f ? 1.0f / deg[i] : 0.0f;
        P[i][j] = dinv * acc;
    }
    __syncthreads();
    if (t < NEXP) {
        float a = 0.0f;
        for (int i = 0; i < NEXP; i++) a += P[i][t];
        u[t] = a / (float)NEXP;
    }
    __syncthreads();
    if (t < NEXP) {
        float a = 0.0f;
        for (int i = 0; i < NEXP; i++) a += u[i] * P[i][t];
        g_v[t] = a;
    }
    if (t == 0) {
        float s = 0.0f;
        for (int i = 0; i < NEXP; i++) s += u[i];
        g_s = s;
    }
}

// ---------------- tiny GEMVs -----------------------------------------------
__global__ void gemv_tb_kernel(const float* __restrict__ W1,
                               const float* __restrict__ b0) {
    int j = blockIdx.x;
    float acc = 0.0f;
    for (int k = threadIdx.x; k < DIM; k += 128)
        acc += W1[j * DIM + k] * b0[k];
    for (int o = 16; o; o >>= 1) acc += __shfl_xor_sync(0xffffffffu, acc, o);
    __shared__ float sm[4];
    if ((threadIdx.x & 31) == 0) sm[threadIdx.x >> 5] = acc;
    __syncthreads();
    if (threadIdx.x == 0) g_tb[j] = sm[0] + sm[1] + sm[2] + sm[3];
}

__global__ void gemv_bf_kernel(const float* __restrict__ Wc,
                               const float* __restrict__ b1,
                               const float* __restrict__ cb) {
    int i = blockIdx.x;
    float s = g_s;
    float acc = 0.0f;
    for (int j = threadIdx.x; j < DIM; j += 128)
        acc += Wc[i * DIM + j] * (s * g_tb[j] + b1[j]);
    for (int o = 16; o; o >>= 1) acc += __shfl_xor_sync(0xffffffffu, acc, o);
    __shared__ float sm[4];
    if ((threadIdx.x & 31) == 0) sm[threadIdx.x >> 5] = acc;
    __syncthreads();
    if (threadIdx.x == 0) g_bf[i] = sm[0] + sm[1] + sm[2] + sm[3] + cb[i];
}

// ---------------- hi/lo bf16 split -----------------------------------------
__device__ __forceinline__ void split_bf16(float x, __nv_bfloat16& h,
                                           __nv_bfloat16& l) {
    h = __float2bfloat16(x);
    l = __float2bfloat16(x - __bfloat162float(h));
}

// ---------------- weighted expert reduce -> bf16 hi/lo ---------------------
__global__ void reduce_convert_kernel(const float* __restrict__ x) {
    int idx = blockIdx.x * blockDim.x + threadIdx.x;  // over TOKENS*128 float4
    int n  = idx >> 7;
    int d4 = idx & 127;
    const float4* base =
        reinterpret_cast<const float4*>(x) + (size_t)n * NEXP * 128 + d4;
    float4 acc = make_float4(0.f, 0.f, 0.f, 0.f);
#pragma unroll
    for (int e = 0; e < NEXP; e++) {
        float4 v = base[(size_t)e * 128];
        float  w = g_v[e];
        acc.x += w * v.x; acc.y += w * v.y; acc.z += w * v.z; acc.w += w * v.w;
    }
    __nv_bfloat16 h0, h1, h2, h3, l0, l1, l2, l3;
    split_bf16(acc.x, h0, l0); split_bf16(acc.y, h1, l1);
    split_bf16(acc.z, h2, l2); split_bf16(acc.w, h3, l3);
    __nv_bfloat162* mh = reinterpret_cast<__nv_bfloat162*>(g_mh);
    __nv_bfloat162* ml = reinterpret_cast<__nv_bfloat162*>(g_ml);
    mh[idx * 2 + 0] = __halves2bfloat162(h0, h1);
    mh[idx * 2 + 1] = __halves2bfloat162(h2, h3);
    ml[idx * 2 + 0] = __halves2bfloat162(l0, l1);
    ml[idx * 2 + 1] = __halves2bfloat162(l2, l3);
}

// ---------------- split-K 512^3 SGEMM (NN) ----------------------------------
// Stage 1: partials of T1 = W1 @ W0  -> g_part[z]
__global__ __launch_bounds__(256) void sgemm512_sk(const float* __restrict__ A,
                                                   const float* __restrict__ B) {
    __shared__ float As[16][68];
    __shared__ float Bs[16][68];
    const int tid = threadIdx.x;
    const int bm = blockIdx.y * 64, bn = blockIdx.x * 64;
    const int kz = blockIdx.z * 128;
    const int tx = tid & 15, ty = tid >> 4;

    float acc[4][4];
#pragma unroll
    for (int i = 0; i < 4; i++)
#pragma unroll
        for (int j = 0; j < 4; j++) acc[i][j] = 0.0f;

    for (int k0 = kz; k0 < kz + 128; k0 += 16) {
        {
            int row = tid >> 2, c4 = tid & 3;
            float4 v = *reinterpret_cast<const float4*>(
                &A[(size_t)(bm + row) * DIM + k0 + c4 * 4]);
            As[c4 * 4 + 0][row] = v.x; As[c4 * 4 + 1][row] = v.y;
            As[c4 * 4 + 2][row] = v.z; As[c4 * 4 + 3][row] = v.w;
        }
        {
            int krow = tid >> 4, c4 = tid & 15;
            float4 v = *reinterpret_cast<const float4*>(
                &B[(size_t)(k0 + krow) * DIM + bn + c4 * 4]);
            *reinterpret_cast<float4*>(&Bs[krow][c4 * 4]) = v;
        }
        __syncthreads();
#pragma unroll
        for (int k = 0; k < 16; k++) {
            float ra[4], rb[4];
#pragma unroll
            for (int i = 0; i < 4; i++) ra[i] = As[k][ty * 4 + i];
#pragma unroll
            for (int j = 0; j < 4; j++) rb[j] = Bs[k][tx * 4 + j];
#pragma unroll
            for (int i = 0; i < 4; i++)
#pragma unroll
                for (int j = 0; j < 4; j++) acc[i][j] += ra[i] * rb[j];
        }
        __syncthreads();
    }
    float* out = g_part + (size_t)blockIdx.z * DIM * DIM;
#pragma unroll
    for (int i = 0; i < 4; i++) {
        int row = bm + ty * 4 + i;
        float4 v = make_float4(acc[i][0], acc[i][1], acc[i][2], acc[i][3]);
        *reinterpret_cast<float4*>(&out[(size_t)row * DIM + bn + tx * 4]) = v;
    }
}

// Stage 2: partials of Wf = Wc @ T1, where T1 = sum of 4 g_part slices
// (B-tile load sums the partials on the fly; they are L2-resident).
__global__ __launch_bounds__(256) void sgemm512_sk2(const float* __restrict__ A) {
    __shared__ float As[16][68];
    __shared__ float Bs[16][68];
    const int tid = threadIdx.x;
    const int bm = blockIdx.y * 64, bn = blockIdx.x * 64;
    const int kz = blockIdx.z * 128;
    const int tx = tid & 15, ty = tid >> 4;

    float acc[4][4];
#pragma unroll
    for (int i = 0; i < 4; i++)
#pragma unroll
        for (int j = 0; j < 4; j++) acc[i][j] = 0.0f;

    for (int k0 = kz; k0 < kz + 128; k0 += 16) {
        {
            int row = tid >> 2, c4 = tid & 3;
            float4 v = *reinterpret_cast<const float4*>(
                &A[(size_t)(bm + row) * DIM + k0 + c4 * 4]);
            As[c4 * 4 + 0][row] = v.x; As[c4 * 4 + 1][row] = v.y;
            As[c4 * 4 + 2][row] = v.z; As[c4 * 4 + 3][row] = v.w;
        }
        {
            int krow = tid >> 4, c4 = tid & 15;
            size_t off = (size_t)(k0 + krow) * DIM + bn + c4 * 4;
            float4 a = *reinterpret_cast<const float4*>(&g_part[off]);
            float4 b = *reinterpret_cast<const float4*>(&g_part[off + 262144]);
            float4 c = *reinterpret_cast<const float4*>(&g_part[off + 524288]);
            float4 d = *reinterpret_cast<const float4*>(&g_part[off + 786432]);
            float4 v = make_float4(a.x + b.x + c.x + d.x, a.y + b.y + c.y + d.y,
                                   a.z + b.z + c.z + d.z, a.w + b.w + c.w + d.w);
            *reinterpret_cast<float4*>(&Bs[krow][c4 * 4]) = v;
        }
        __syncthreads();
#pragma unroll
        for (int k = 0; k < 16; k++) {
            float ra[4], rb[4];
#pragma unroll
            for (int i = 0; i < 4; i++) ra[i] = As[k][ty * 4 + i];
#pragma unroll
            for (int j = 0; j < 4; j++) rb[j] = Bs[k][tx * 4 + j];
#pragma unroll
            for (int i = 0; i < 4; i++)
#pragma unroll
                for (int j = 0; j < 4; j++) acc[i][j] += ra[i] * rb[j];
        }
        __syncthreads();
    }
    float* out = g_part2 + (size_t)blockIdx.z * DIM * DIM;
#pragma unroll
    for (int i = 0; i < 4; i++) {
        int row = bm + ty * 4 + i;
        float4 v = make_float4(acc[i][0], acc[i][1], acc[i][2], acc[i][3]);
        *reinterpret_cast<float4*>(&out[(size_t)row * DIM + bn + tx * 4]) = v;
    }
}

__global__ void combine_to_W(void) {
    int i = blockIdx.x * 256 + threadIdx.x;  // float4 index, 65536 total
    const float4* p = reinterpret_cast<const float4*>(g_part2);
    float4 a = p[i], b = p[i + 65536], c = p[i + 131072], d = p[i + 196608];
    float4 s = make_float4(a.x + b.x + c.x + d.x, a.y + b.y + c.y + d.y,
                           a.z + b.z + c.z + d.z, a.w + b.w + c.w + d.w);
    __nv_bfloat16 h0, h1, h2, h3, l0, l1, l2, l3;
    split_bf16(s.x, h0, l0); split_bf16(s.y, h1, l1);
    split_bf16(s.z, h2, l2); split_bf16(s.w, h3, l3);
    __nv_bfloat162* wh = reinterpret_cast<__nv_bfloat162*>(g_wh);
    __nv_bfloat162* wl = reinterpret_cast<__nv_bfloat162*>(g_wl);
    wh[i * 2 + 0] = __halves2bfloat162(h0, h1);
    wh[i * 2 + 1] = __halves2bfloat162(h2, h3);
    wl[i * 2 + 0] = __halves2bfloat162(l0, l1);
    wl[i * 2 + 1] = __halves2bfloat162(l2, l3);
}

// ---------------- exact GELU -----------------------------------------------
__device__ __forceinline__ float gelu_exact(float x) {
    return 0.5f * x * (1.0f + erff(x * 0.70710678118654752f));
}

// ---------------- fused HMMA GEMM + bias + GELU + LayerNorm -----------------
// out = LN(gelu(m @ Wf^T + bf)) ; M=8192, N=512(full row per CTA), K=512.
// bf16 hi/lo compensated: acc = Ah*Bh + Ah*Bl + Al*Bh in fp32.
// CTA tile 64x512, 8 warps: warp tile 16(M) x 256(N). BK=32, double buffer.
#define BK   32
#define BKP  40                       // padded row stride (bf16 elems)
#define A_T_E (64 * BKP)              // 2560 elems = 5120 B per A tile
#define B_T_E (512 * BKP)             // 20480 elems = 40960 B per B tile
#define OFF_AH 0
#define OFF_AL (A_T_E * 2)            // 5120
#define OFF_BH (2 * A_T_E * 2)        // 10240
#define OFF_BL (OFF_BH + B_T_E * 2)   // 51200
#define STG_B  (OFF_BL + B_T_E * 2)   // 92160 bytes per stage
#define GEMM_SMEM_B (2 * STG_B)       // 184320 bytes

__device__ __forceinline__ void cp_async16(uint32_t saddr, const void* gptr) {
    asm volatile("cp.async.cg.shared.global [%0], [%1], 16;\n"
                 :: "r"(saddr), "l"(gptr));
}
__device__ __forceinline__ void cp_commit() {
    asm volatile("cp.async.commit_group;\n");
}
template <int N>
__device__ __forceinline__ void cp_wait() {
    asm volatile("cp.async.wait_group %0;\n" :: "n"(N));
}
__device__ __forceinline__ void ldsm_x4(uint32_t* r, uint32_t addr) {
    asm volatile(
        "ldmatrix.sync.aligned.m8n8.x4.shared.b16 {%0,%1,%2,%3}, [%4];"
        : "=r"(r[0]), "=r"(r[1]), "=r"(r[2]), "=r"(r[3]) : "r"(addr));
}
__device__ __forceinline__ void mma_bf16(float* d, const uint32_t* a,
                                         uint32_t b0, uint32_t b1) {
    asm volatile(
        "mma.sync.aligned.m16n8k16.row.col.f32.bf16.bf16.f32 "
        "{%0,%1,%2,%3}, {%4,%5,%6,%7}, {%8,%9}, {%0,%1,%2,%3};"
        : "+f"(d[0]), "+f"(d[1]), "+f"(d[2]), "+f"(d[3])
        : "r"(a[0]), "r"(a[1]), "r"(a[2]), "r"(a[3]), "r"(b0), "r"(b1));
}
__device__ __forceinline__ uint32_t smem_u32(const void* p) {
    uint32_t a;
    asm("{ .reg .u64 t; cvta.to.shared.u64 t, %1; cvt.u32.u64 %0, t; }"
        : "=r"(a) : "l"(p));
    return a;
}

__global__ __launch_bounds__(256, 1) void gemm_ln(
    const float* __restrict__ gamma, const float* __restrict__ beta,
    float* __restrict__ out) {
    extern __shared__ __nv_bfloat16 smem[];
    __shared__ float red[64][2][2];  // [row][n-half][sum,sq]
    const uint32_t sb = smem_u32(smem);
    const int tid  = threadIdx.x;
    const int wid  = tid >> 5;
    const int lane = tid & 31;
    const int bm = blockIdx.x * 64;
    const int wm = (wid & 3) * 16;    // warp m offset (0..48)
    const int wn = (wid >> 2) * 256;  // warp n offset (0 or 256)

    float acc[32][4];
#pragma unroll
    for (int j = 0; j < 32; j++)
#pragma unroll
        for (int r = 0; r < 4; r++) acc[j][r] = 0.0f;

    // ldmatrix lane address components
    const int lrow = (lane & 7) + ((lane >> 3) & 1) * 8;
    const int lcol = (lane >> 4) * 8;
    const uint32_t a_eoff = (uint32_t)(((wm + lrow) * BKP + lcol) * 2);
    const uint32_t b_eoff = (uint32_t)(((wn + lrow) * BKP + lcol) * 2);

    // cp.async mapping: thread covers row = tid>>2 (+64*i for B), u = tid&3
    const int r_ld = tid >> 2;
    const int u_ld = tid & 3;

    auto issue_stage = [&](int c, int buf) {
        const int k0 = c * BK;
        const uint32_t stg = sb + (uint32_t)(buf * STG_B);
        {   // A: 64 rows
            const uint32_t doff = (uint32_t)((r_ld * BKP + u_ld * 8) * 2);
            const __nv_bfloat16* sAh =
                g_mh + (size_t)(bm + r_ld) * DIM + k0 + u_ld * 8;
            const __nv_bfloat16* sAl =
                g_ml + (size_t)(bm + r_ld) * DIM + k0 + u_ld * 8;
            cp_async16(stg + OFF_AH + doff, sAh);
            cp_async16(stg + OFF_AL + doff, sAl);
        }
#pragma unroll
        for (int i = 0; i < 8; i++) {  // B: 512 rows
            const int r = r_ld + i * 64;
            const uint32_t doff = (uint32_t)((r * BKP + u_ld * 8) * 2);
            const __nv_bfloat16* sBh =
                g_wh + (size_t)r * DIM + k0 + u_ld * 8;
            const __nv_bfloat16* sBl =
                g_wl + (size_t)r * DIM + k0 + u_ld * 8;
            cp_async16(stg + OFF_BH + doff, sBh);
            cp_async16(stg + OFF_BL + doff, sBl);
        }
    };

    issue_stage(0, 0);
    cp_commit();

    const int NSTG = DIM / BK;  // 16
    for (int c = 0; c < NSTG; c++) {
        const int buf = c & 1;
        if (c + 1 < NSTG) { issue_stage(c + 1, (c + 1) & 1); cp_commit(); }
        if (c + 1 < NSTG) cp_wait<1>(); else cp_wait<0>();
        __syncthreads();

        const uint32_t stg = sb + (uint32_t)(buf * STG_B);
        const uint32_t pAh = stg + OFF_AH + a_eoff;
        const uint32_t pAl = stg + OFF_AL + a_eoff;
        const uint32_t pBh = stg + OFF_BH + b_eoff;
        const uint32_t pBl = stg + OFF_BL + b_eoff;

#pragma unroll
        for (int kk = 0; kk < BK; kk += 16) {
            const uint32_t ko = (uint32_t)(kk * 2);
            uint32_t Ahf[4], Alf[4];
            ldsm_x4(Ahf, pAh + ko);
            ldsm_x4(Alf, pAl + ko);

            uint32_t Bh[2][4], Bl[2][4];
            ldsm_x4(Bh[0], pBh + ko);
            ldsm_x4(Bl[0], pBl + ko);
#pragma unroll
            for (int g = 0; g < 16; g++) {
                const int cur = g & 1;
                if (g < 15) {
                    const uint32_t o = (uint32_t)(((g + 1) * 16 * BKP) * 2) + ko;
                    ldsm_x4(Bh[cur ^ 1], pBh + o);
                    ldsm_x4(Bl[cur ^ 1], pBl + o);
                }
#pragma unroll
                for (int hf = 0; hf < 2; hf++) {
                    const int n8 = g * 2 + hf;
                    const uint32_t bh0 = Bh[cur][hf], bh1 = Bh[cur][hf + 2];
                    const uint32_t bl0 = Bl[cur][hf], bl1 = Bl[cur][hf + 2];
                    mma_bf16(acc[n8], Ahf, bh0, bh1);
                    mma_bf16(acc[n8], Ahf, bl0, bl1);
                    mma_bf16(acc[n8], Alf, bh0, bh1);
                }
            }
        }
        __syncthreads();
    }

    // ---------------- epilogue: bias + GELU + LayerNorm ---------------------
    const int q = lane >> 2;
    float sum0 = 0.f, sq0 = 0.f, sum1 = 0.f, sq1 = 0.f;
#pragma unroll
    for (int n8 = 0; n8 < 32; n8++) {
        const int col = wn + n8 * 8 + (lane & 3) * 2;
        const float2 bv = *reinterpret_cast<const float2*>(&g_bf[col]);
        float g0 = gelu_exact(acc[n8][0] + bv.x);
        float g1 = gelu_exact(acc[n8][1] + bv.y);
        float g2 = gelu_exact(acc[n8][2] + bv.x);
        float g3 = gelu_exact(acc[n8][3] + bv.y);
        acc[n8][0] = g0; acc[n8][1] = g1; acc[n8][2] = g2; acc[n8][3] = g3;
        sum0 += g0 + g1; sq0 += g0 * g0 + g1 * g1;
        sum1 += g2 + g3; sq1 += g2 * g2 + g3 * g3;
    }
#pragma unroll
    for (int o = 1; o <= 2; o <<= 1) {
        sum0 += __shfl_xor_sync(0xffffffffu, sum0, o);
        sq0  += __shfl_xor_sync(0xffffffffu, sq0, o);
        sum1 += __shfl_xor_sync(0xffffffffu, sum1, o);
        sq1  += __shfl_xor_sync(0xffffffffu, sq1, o);
    }
    const int half = wid >> 2;
    if ((lane & 3) == 0) {
        red[wm + q][half][0] = sum0; red[wm + q][half][1] = sq0;
        red[wm + q + 8][half][0] = sum1; red[wm + q + 8][half][1] = sq1;
    }
    __syncthreads();
    const float inv_d = 1.0f / (float)DIM;
    float mu0 = (red[wm + q][0][0] + red[wm + q][1][0]) * inv_d;
    float ms0 = (red[wm + q][0][1] + red[wm + q][1][1]) * inv_d;
    float iv0 = rsqrtf(ms0 - mu0 * mu0 + LN_EPS);
    float mu1 = (red[wm + q + 8][0][0] + red[wm + q + 8][1][0]) * inv_d;
    float ms1 = (red[wm + q + 8][0][1] + red[wm + q + 8][1][1]) * inv_d;
    float iv1 = rsqrtf(ms1 - mu1 * mu1 + LN_EPS);

    const int r0 = bm + wm + q;
    const int r1 = r0 + 8;
#pragma unroll
    for (int n8 = 0; n8 < 32; n8++) {
        const int col = wn + n8 * 8 + (lane & 3) * 2;
        const float2 ga = *reinterpret_cast<const float2*>(&gamma[col]);
        const float2 be = *reinterpret_cast<const float2*>(&beta[col]);
        float2 o0, o1;
        o0.x = (acc[n8][0] - mu0) * iv0 * ga.x + be.x;
        o0.y = (acc[n8][1] - mu0) * iv0 * ga.y + be.y;
        o1.x = (acc[n8][2] - mu1) * iv1 * ga.x + be.x;
        o1.y = (acc[n8][3] - mu1) * iv1 * ga.y + be.y;
        *reinterpret_cast<float2*>(&out[(size_t)r0 * DIM + col]) = o0;
        *reinterpret_cast<float2*>(&out[(size_t)r1 * DIM + col]) = o1;
    }
}

// ---------------- launcher ---------------------------------------------------
extern "C" void kernel_launch(void* const* d_in, const int* in_sizes, int n_in,
                              void* d_out, int out_size) {
    const float* x     = (const float*)d_in[0];
    const float* hw    = (const float*)d_in[1];
    const float* hb    = (const float*)d_in[2];
    const float* cw    = (const float*)d_in[3];
    const float* cbias = (const float*)d_in[4];
    const float* lg    = (const float*)d_in[5];
    const float* lb    = (const float*)d_in[6];
    const int*   nodes = (const int*)d_in[7];
    const int*   edges = (const int*)d_in[8];
    const int    nn    = in_sizes[7];
    float*       out   = (float*)d_out;

    const float* W0 = hw;
    const float* W1 = hw + DIM * DIM;
    const float* b0 = hb;
    const float* b1 = hb + DIM;

    cudaFuncSetAttribute(gemm_ln, cudaFuncAttributeMaxDynamicSharedMemorySize,
                         GEMM_SMEM_B);

    // 1) hyperedge structure -> v, s
    structure_kernel<<<1, 256>>>(nodes, edges, nn);

    // 2) weighted expert reduce -> m hi/lo bf16
    reduce_convert_kernel<<<TOKENS * 128 / 256, 256>>>(x);

    // 3) Wf = Wc @ (W1 @ W0), split-K (combine of T1 fused into stage 2)
    {
        dim3 grid(8, 8, 4);
        sgemm512_sk<<<grid, 256>>>(W1, W0);
        sgemm512_sk2<<<grid, 256>>>(cw);
        combine_to_W<<<256, 256>>>();
    }

    // 4) fused bias
    gemv_tb_kernel<<<DIM, 128>>>(W1, b0);
    gemv_bf_kernel<<<DIM, 128>>>(cw, b1, cbias);

    // 5) main HMMA GEMM + bias + GELU + LayerNorm -> out
    gemm_ln<<<TOKENS / 64, 256, GEMM_SMEM_B>>>(lg, lb, out);
}